// round 2
// baseline (speedup 1.0000x reference)
#include <cuda_runtime.h>

// ---------------------------------------------------------------------------
// StDimLocalLocalContrastModel: P=64 positions, B=1024, C=256, HID=512
//   a[m,c]      (m = b*64+p)  gathered from anchor[b,c,p]
//   hidden      = relu(a @ W1^T + b1)           [65536,512]
//   aprime      = a + hidden @ W2^T + b2        [65536,256]
//   pred        = aprime @ Ww^T                 [65536,256]
//   logits[p]   = pred_p @ pos_p^T              64 x [1024,1024]
//   out         = logits - rowmax(logits)
// ---------------------------------------------------------------------------

#define BM 128
#define BN 128
#define BK 16

// scratch (device globals: allocation-free per harness rules)
// g_pred aliases g_a: gathered anchor is dead after GEMM2 consumes the residual.
__device__ float g_a     [16777216];   // [65536,256]  (later reused as pred)
__device__ float g_pos   [16777216];   // [65536,256]
__device__ float g_hidden[33554432];   // [65536,512]
__device__ float g_aprime[16777216];   // [65536,256]

// in: [1024][256][64]  ->  out: [1024][64][256]   (out[(b*64+p)*256+c] = in[b][c][p])
// blockIdx.z selects (src,dst) pair.
__global__ void transpose_kernel(const float* __restrict__ in0, float* __restrict__ out0,
                                 const float* __restrict__ in1, float* __restrict__ out1) {
    __shared__ float t[32][33];
    const float* in  = blockIdx.z ? in1  : in0;
    float*       out = blockIdx.z ? out1 : out0;
    int b  = blockIdx.y;
    int c0 = (blockIdx.x & 7) * 32;
    int p0 = (blockIdx.x >> 3) * 32;
    const float* src = in  + (long)b * 16384;
    float*       dst = out + (long)b * 16384;
    #pragma unroll
    for (int j = 0; j < 32; j += 8)
        t[threadIdx.y + j][threadIdx.x] = src[(c0 + threadIdx.y + j) * 64 + p0 + threadIdx.x];
    __syncthreads();
    #pragma unroll
    for (int j = 0; j < 32; j += 8)
        dst[(p0 + threadIdx.y + j) * 256 + c0 + threadIdx.x] = t[threadIdx.x][threadIdx.y + j];
}

// C[m,n] = sum_k A[m,k] * B[n,k]   (both K-contiguous), optional epilogues.
// MODE 0: plain   MODE 1: relu(acc + bias[n])   MODE 2: acc + bias[n] + resid[m,n]
// Batched via blockIdx.z with element strides batchA/batchB/batchC.
// Assumes M%BM==0, N%BN==0, K%BK==0 (true for all calls here).
template<int MODE>
__global__ __launch_bounds__(256, 2)
void sgemm_kernel(const float* __restrict__ A, long Astride, long batchA,
                  const float* __restrict__ B, long Bstride, long batchB,
                  float* __restrict__ C, long Cstride, long batchC,
                  int K,
                  const float* __restrict__ bias,
                  const float* __restrict__ resid, long resStride)
{
    __shared__ float As[2][BK][BM + 4];
    __shared__ float Bs[2][BK][BN + 4];

    const int tid = threadIdx.x;
    const int tx = tid & 15;
    const int ty = tid >> 4;
    const long z = blockIdx.z;

    const float* Ab = A + z * batchA + (long)blockIdx.y * BM * Astride;
    const float* Bb = B + z * batchB + (long)blockIdx.x * BN * Bstride;

    float acc[8][8];
    #pragma unroll
    for (int i = 0; i < 8; i++)
        #pragma unroll
        for (int j = 0; j < 8; j++) acc[i][j] = 0.0f;

    const int r0 = tid >> 2;        // 0..63
    const int kg = (tid & 3) * 4;   // 0,4,8,12

    // tile loader: 128 rows x 16 k, each thread 2 float4 per matrix
    auto loadTile = [&](int k0, int buf) {
        #pragma unroll
        for (int h = 0; h < 2; h++) {
            int r = r0 + h * 64;
            float4 av = *(const float4*)(Ab + (long)r * Astride + k0 + kg);
            As[buf][kg + 0][r] = av.x;
            As[buf][kg + 1][r] = av.y;
            As[buf][kg + 2][r] = av.z;
            As[buf][kg + 3][r] = av.w;
            float4 bv = *(const float4*)(Bb + (long)r * Bstride + k0 + kg);
            Bs[buf][kg + 0][r] = bv.x;
            Bs[buf][kg + 1][r] = bv.y;
            Bs[buf][kg + 2][r] = bv.z;
            Bs[buf][kg + 3][r] = bv.w;
        }
    };

    loadTile(0, 0);
    __syncthreads();

    const int nk = K / BK;
    int buf = 0;
    for (int kt = 0; kt < nk; kt++) {
        if (kt + 1 < nk) loadTile((kt + 1) * BK, buf ^ 1);
        #pragma unroll
        for (int k = 0; k < BK; k++) {
            float4 a0 = *(const float4*)&As[buf][k][ty * 8];
            float4 a1 = *(const float4*)&As[buf][k][ty * 8 + 4];
            float4 b0 = *(const float4*)&Bs[buf][k][tx * 8];
            float4 b1 = *(const float4*)&Bs[buf][k][tx * 8 + 4];
            float af[8] = {a0.x, a0.y, a0.z, a0.w, a1.x, a1.y, a1.z, a1.w};
            float bf[8] = {b0.x, b0.y, b0.z, b0.w, b1.x, b1.y, b1.z, b1.w};
            #pragma unroll
            for (int i = 0; i < 8; i++)
                #pragma unroll
                for (int j = 0; j < 8; j++)
                    acc[i][j] += af[i] * bf[j];
        }
        __syncthreads();
        buf ^= 1;
    }

    // epilogue
    const long row0 = (long)blockIdx.y * BM + ty * 8;
    const int  col0 = blockIdx.x * BN + tx * 8;
    float* Cb = C + z * batchC;

    float bj[8];
    if (MODE == 1 || MODE == 2) {
        #pragma unroll
        for (int j = 0; j < 8; j++) bj[j] = bias[col0 + j];
    }

    #pragma unroll
    for (int i = 0; i < 8; i++) {
        long row = row0 + i;
        float v[8];
        #pragma unroll
        for (int j = 0; j < 8; j++) v[j] = acc[i][j];
        if (MODE == 1) {
            #pragma unroll
            for (int j = 0; j < 8; j++) v[j] = fmaxf(v[j] + bj[j], 0.0f);
        } else if (MODE == 2) {
            float4 r0v = *(const float4*)(resid + row * resStride + col0);
            float4 r1v = *(const float4*)(resid + row * resStride + col0 + 4);
            float rr[8] = {r0v.x, r0v.y, r0v.z, r0v.w, r1v.x, r1v.y, r1v.z, r1v.w};
            #pragma unroll
            for (int j = 0; j < 8; j++) v[j] = v[j] + bj[j] + rr[j];
        }
        float4 o0 = make_float4(v[0], v[1], v[2], v[3]);
        float4 o1 = make_float4(v[4], v[5], v[6], v[7]);
        *(float4*)(Cb + row * Cstride + col0)     = o0;
        *(float4*)(Cb + row * Cstride + col0 + 4) = o1;
    }
}

// one block per output row of 1024: subtract row max in-place
__global__ void rowmax_kernel(float* __restrict__ out) {
    long row = blockIdx.x;
    float4* rp = (float4*)(out + row * 1024);
    float4 v = rp[threadIdx.x];
    float m = fmaxf(fmaxf(v.x, v.y), fmaxf(v.z, v.w));
    #pragma unroll
    for (int o = 16; o; o >>= 1) m = fmaxf(m, __shfl_xor_sync(0xffffffffu, m, o));
    __shared__ float sm[8];
    if ((threadIdx.x & 31) == 0) sm[threadIdx.x >> 5] = m;
    __syncthreads();
    float mm = sm[0];
    #pragma unroll
    for (int i = 1; i < 8; i++) mm = fmaxf(mm, sm[i]);
    v.x -= mm; v.y -= mm; v.z -= mm; v.w -= mm;
    rp[threadIdx.x] = v;
}

extern "C" void kernel_launch(void* const* d_in, const int* in_sizes, int n_in,
                              void* d_out, int out_size) {
    const float* anchor   = (const float*)d_in[0];
    const float* positive = (const float*)d_in[1];
    const float* W1 = (const float*)d_in[2];
    const float* b1 = (const float*)d_in[3];
    const float* W2 = (const float*)d_in[4];
    const float* b2 = (const float*)d_in[5];
    const float* Ww = (const float*)d_in[6];
    float* out = (float*)d_out;

    float *ga, *gpos, *ghid, *gap;
    cudaGetSymbolAddress((void**)&ga,   g_a);
    cudaGetSymbolAddress((void**)&gpos, g_pos);
    cudaGetSymbolAddress((void**)&ghid, g_hidden);
    cudaGetSymbolAddress((void**)&gap,  g_aprime);
    float* gpred = ga;   // alias: anchor gather dead after GEMM2

    dim3 tb(32, 8);
    transpose_kernel<<<dim3(16, 1024, 2), tb>>>(anchor, ga, positive, gpos);

    // GEMM1: hidden = relu(a @ W1^T + b1)   [65536,512]
    sgemm_kernel<1><<<dim3(4, 512, 1), 256>>>(ga, 256, 0, W1, 256, 0,
                                              ghid, 512, 0, 256, b1, nullptr, 0);
    // GEMM2: aprime = a + hidden @ W2^T + b2   [65536,256]
    sgemm_kernel<2><<<dim3(2, 512, 1), 256>>>(ghid, 512, 0, W2, 512, 0,
                                              gap, 256, 0, 512, b2, ga, 256);
    // GEMM3: pred = aprime @ Ww^T   [65536,256]  (writes over g_a)
    sgemm_kernel<0><<<dim3(2, 512, 1), 256>>>(gap, 256, 0, Ww, 256, 0,
                                              gpred, 256, 0, 256, nullptr, nullptr, 0);
    // GEMM4 (batched over p=64): logits[p] = pred_p @ pos_p^T   [1024,1024]
    sgemm_kernel<0><<<dim3(8, 8, 64), 256>>>(gpred, 16384, 256, gpos, 16384, 256,
                                             out, 1024, 1048576, 256, nullptr, nullptr, 0);
    // subtract row max in-place
    rowmax_kernel<<<65536, 256>>>(out);
}

// round 6
// speedup vs baseline: 1.9435x; 1.9435x over previous
#include <cuda_runtime.h>
#include <cuda_bf16.h>

typedef __nv_bfloat16 bf16;

// ---------------------------------------------------------------------------
// StDimLocalLocalContrastModel via mma.sync bf16 (split-2 emulated fp32).
// ptxas target is sm_103 (no 'a' features): tcgen05 unavailable, HMMA path used.
//   P=64, B=1024, C=256, HID=512, M = B*P = 65536
// ---------------------------------------------------------------------------

#define BM 128
#define BN 128
#define BKK 32
#define PAD_ROW 40                    // bf16 elems per smem row (32 data + 8 pad)
#define TILE_BF (128 * PAD_ROW)       // elems per tile per stage
#define SMEM_BYTES (8 * TILE_BF * 2)  // 4 tensors x 2 stages x 10240 B = 81920

// ---- scratch (device globals; allocation-free) ----
__device__ bf16 g_a_hi  [16777216];   // [65536,256] anchor -> later pred (alias)
__device__ bf16 g_a_lo  [16777216];
__device__ bf16 g_pos_hi[16777216];   // [65536,256]
__device__ bf16 g_pos_lo[16777216];
__device__ bf16 g_hid_hi[33554432];   // [65536,512]
__device__ bf16 g_hid_lo[33554432];
__device__ bf16 g_ap_hi [16777216];   // [65536,256]
__device__ bf16 g_ap_lo [16777216];
__device__ bf16 g_w1_hi [131072], g_w1_lo[131072];   // [512,256]
__device__ bf16 g_w2_hi [131072], g_w2_lo[131072];   // [256,512]
__device__ bf16 g_ww_hi [65536],  g_ww_lo[65536];    // [256,256]

// ---- PTX helpers (all non-'a' ISA: cp.async sm_80, ldmatrix sm_75, mma sm_80) --
__device__ __forceinline__ void cp16(const bf16* src, bf16* dst) {
    unsigned d = (unsigned)__cvta_generic_to_shared(dst);
    asm volatile("cp.async.cg.shared.global [%0], [%1], 16;" :: "r"(d), "l"(src));
}
__device__ __forceinline__ void cp_commit() { asm volatile("cp.async.commit_group;"); }
template<int N> __device__ __forceinline__ void cp_wait() {
    asm volatile("cp.async.wait_group %0;" :: "n"(N));
}
__device__ __forceinline__ void ldsm4(unsigned* r, const bf16* p) {
    unsigned a = (unsigned)__cvta_generic_to_shared(p);
    asm volatile("ldmatrix.sync.aligned.m8n8.x4.shared.b16 {%0,%1,%2,%3}, [%4];"
        : "=r"(r[0]), "=r"(r[1]), "=r"(r[2]), "=r"(r[3]) : "r"(a));
}
__device__ __forceinline__ void mma_bf16(float* d, const unsigned* a, const unsigned* b) {
    asm volatile(
        "mma.sync.aligned.m16n8k16.row.col.f32.bf16.bf16.f32 "
        "{%0,%1,%2,%3}, {%4,%5,%6,%7}, {%8,%9}, {%0,%1,%2,%3};"
        : "+f"(d[0]), "+f"(d[1]), "+f"(d[2]), "+f"(d[3])
        : "r"(a[0]), "r"(a[1]), "r"(a[2]), "r"(a[3]), "r"(b[0]), "r"(b[1]));
}

// ---------------------------------------------------------------------------
// mma_gemm: C[m,n] = sum_k A[m,k]*B[n,k], split-bf16 emulated fp32.
// MODE 0: fp32 out   MODE 1: relu(acc+bias)->hi/lo
// MODE 2: acc+bias+resid->hi/lo   MODE 3: plain->hi/lo
// CTA 128x128, BK=32, 8 warps (2x4), warp tile 64x32.
// ---------------------------------------------------------------------------
template<int MODE>
__global__ __launch_bounds__(256, 1)
void mma_gemm(const bf16* __restrict__ Ahi, const bf16* __restrict__ Alo, long As, long Ab,
              const bf16* __restrict__ Bhi, const bf16* __restrict__ Blo, long Bs, long Bb,
              int K,
              float* __restrict__ Cf, long Cs, long Cb,
              bf16* __restrict__ Ohi, bf16* __restrict__ Olo, long Os,
              const float* __restrict__ bias,
              const bf16* __restrict__ Rhi, const bf16* __restrict__ Rlo, long Rs)
{
    extern __shared__ bf16 smem[];
    bf16* sAh = smem;
    bf16* sAl = smem + 2 * TILE_BF;
    bf16* sBh = smem + 4 * TILE_BF;
    bf16* sBl = smem + 6 * TILE_BF;

    const int tid = threadIdx.x;
    const int wid = tid >> 5;
    const int lane = tid & 31;
    const long z = blockIdx.z;

    const bf16* gAh = Ahi + z * Ab + (long)blockIdx.y * BM * As;
    const bf16* gAl = Alo + z * Ab + (long)blockIdx.y * BM * As;
    const bf16* gBh = Bhi + z * Bb + (long)blockIdx.x * BN * Bs;
    const bf16* gBl = Blo + z * Bb + (long)blockIdx.x * BN * Bs;

    // loader: 128 rows x 32 k = 512 16B chunks per tile, 2 per thread
    auto loadTile = [&](const bf16* g, long stride, int k0, bf16* dst) {
        #pragma unroll
        for (int it = 0; it < 2; it++) {
            int c = tid + it * 256;
            int r = c >> 2, kc = c & 3;
            cp16(g + (long)r * stride + k0 + kc * 8, dst + r * PAD_ROW + kc * 8);
        }
    };
    auto loadAll = [&](int kt, int s) {
        int k0 = kt * BKK;
        loadTile(gAh, As, k0, sAh + s * TILE_BF);
        loadTile(gAl, As, k0, sAl + s * TILE_BF);
        loadTile(gBh, Bs, k0, sBh + s * TILE_BF);
        loadTile(gBl, Bs, k0, sBl + s * TILE_BF);
        cp_commit();
    };

    float acc[4][4][4];
    #pragma unroll
    for (int i = 0; i < 4; i++)
        #pragma unroll
        for (int j = 0; j < 4; j++)
            #pragma unroll
            for (int q = 0; q < 4; q++) acc[i][j][q] = 0.0f;

    const int wm = (wid >> 2) * 64;            // warp m offset
    const int wn = (wid & 3) * 32;             // warp n offset
    // ldmatrix lane->address mapping (see PTX spec m16n8k16 row.col frags)
    const int aRow = (lane & 7) + ((lane >> 3) & 1) * 8;
    const int aColH = ((lane >> 4) & 1) * 8;
    const int bRow = (lane & 7) + ((lane >> 4) & 1) * 8;
    const int bColH = ((lane >> 3) & 1) * 8;

    loadAll(0, 0);

    const int nk = K / BKK;
    for (int kt = 0; kt < nk; kt++) {
        if (kt + 1 < nk) { loadAll(kt + 1, (kt + 1) & 1); cp_wait<1>(); }
        else             { cp_wait<0>(); }
        __syncthreads();

        const int s = kt & 1;
        const bf16* Ah = sAh + s * TILE_BF;
        const bf16* Al = sAl + s * TILE_BF;
        const bf16* Bh = sBh + s * TILE_BF;
        const bf16* Bl = sBl + s * TILE_BF;

        #pragma unroll
        for (int kh = 0; kh < BKK; kh += 16) {
            unsigned Bh4[2][4], Bl4[2][4];
            #pragma unroll
            for (int nj = 0; nj < 2; nj++) {
                const bf16* bp = Bh + (wn + nj * 16 + bRow) * PAD_ROW + kh + bColH;
                ldsm4(Bh4[nj], bp);
                const bf16* bq = Bl + (wn + nj * 16 + bRow) * PAD_ROW + kh + bColH;
                ldsm4(Bl4[nj], bq);
            }
            #pragma unroll
            for (int mi = 0; mi < 4; mi++) {
                unsigned Ah4[4], Al4[4];
                const bf16* ap = Ah + (wm + mi * 16 + aRow) * PAD_ROW + kh + aColH;
                ldsm4(Ah4, ap);
                const bf16* aq = Al + (wm + mi * 16 + aRow) * PAD_ROW + kh + aColH;
                ldsm4(Al4, aq);
                #pragma unroll
                for (int ni = 0; ni < 4; ni++) {
                    const unsigned* bh = &Bh4[ni >> 1][(ni & 1) * 2];
                    const unsigned* bl = &Bl4[ni >> 1][(ni & 1) * 2];
                    mma_bf16(acc[mi][ni], Ah4, bh);   // hi*hi
                    mma_bf16(acc[mi][ni], Ah4, bl);   // hi*lo
                    mma_bf16(acc[mi][ni], Al4, bh);   // lo*hi
                }
            }
        }
        __syncthreads();
    }

    // ---- epilogue ----
    const int quad = lane >> 2, qt = lane & 3;
    const long rowBase = (long)blockIdx.y * BM + wm;
    const int colBase = blockIdx.x * BN + wn;

    #pragma unroll
    for (int mi = 0; mi < 4; mi++) {
        #pragma unroll
        for (int ni = 0; ni < 4; ni++) {
            #pragma unroll
            for (int half = 0; half < 2; half++) {
                long m = rowBase + mi * 16 + quad + half * 8;
                int n = colBase + ni * 8 + qt * 2;
                float v0 = acc[mi][ni][half * 2 + 0];
                float v1 = acc[mi][ni][half * 2 + 1];
                if (MODE == 0) {
                    *(float2*)(Cf + z * Cb + m * Cs + n) = make_float2(v0, v1);
                } else {
                    if (MODE == 1) {
                        v0 = fmaxf(v0 + bias[n], 0.0f);
                        v1 = fmaxf(v1 + bias[n + 1], 0.0f);
                    } else if (MODE == 2) {
                        __nv_bfloat162 rh = *(const __nv_bfloat162*)(Rhi + m * Rs + n);
                        __nv_bfloat162 rl = *(const __nv_bfloat162*)(Rlo + m * Rs + n);
                        v0 += bias[n]     + __bfloat162float(rh.x) + __bfloat162float(rl.x);
                        v1 += bias[n + 1] + __bfloat162float(rh.y) + __bfloat162float(rl.y);
                    }
                    bf16 h0 = __float2bfloat16(v0);
                    bf16 h1 = __float2bfloat16(v1);
                    bf16 l0 = __float2bfloat16(v0 - __bfloat162float(h0));
                    bf16 l1 = __float2bfloat16(v1 - __bfloat162float(h1));
                    __nv_bfloat162 hp; hp.x = h0; hp.y = h1;
                    __nv_bfloat162 lp; lp.x = l0; lp.y = l1;
                    *(__nv_bfloat162*)(Ohi + m * Os + n) = hp;
                    *(__nv_bfloat162*)(Olo + m * Os + n) = lp;
                }
            }
        }
    }
}

// ---------------------------------------------------------------------------
// prep: [1024][256][64] fp32 -> hi/lo bf16 [(b*64+p)][c]
// ---------------------------------------------------------------------------
__global__ void transpose_split(const float* __restrict__ in0, bf16* __restrict__ h0, bf16* __restrict__ l0,
                                const float* __restrict__ in1, bf16* __restrict__ h1, bf16* __restrict__ l1) {
    __shared__ float t[32][33];
    const float* in = blockIdx.z ? in1 : in0;
    bf16* oh = blockIdx.z ? h1 : h0;
    bf16* ol = blockIdx.z ? l1 : l0;
    int b  = blockIdx.y;
    int c0 = (blockIdx.x & 7) * 32;
    int p0 = (blockIdx.x >> 3) * 32;
    const float* src = in + (long)b * 16384;
    #pragma unroll
    for (int j = 0; j < 32; j += 8)
        t[threadIdx.y + j][threadIdx.x] = src[(c0 + threadIdx.y + j) * 64 + p0 + threadIdx.x];
    __syncthreads();
    #pragma unroll
    for (int j = 0; j < 32; j += 8) {
        float v = t[threadIdx.x][threadIdx.y + j];
        long rowoff = ((long)b * 64 + p0 + threadIdx.y + j) * 256 + c0 + threadIdx.x;
        bf16 h = __float2bfloat16(v);
        oh[rowoff] = h;
        ol[rowoff] = __float2bfloat16(v - __bfloat162float(h));
    }
}

__global__ void split_w(const float* __restrict__ w, bf16* __restrict__ hi, bf16* __restrict__ lo, int n) {
    int i = blockIdx.x * 256 + threadIdx.x;
    if (i < n) {
        float v = w[i];
        bf16 h = __float2bfloat16(v);
        hi[i] = h;
        lo[i] = __float2bfloat16(v - __bfloat162float(h));
    }
}

// subtract row max in-place, row = 1024 floats
__global__ void rowmax_kernel(float* __restrict__ out) {
    long row = blockIdx.x;
    float4* rp = (float4*)(out + row * 1024);
    float4 v = rp[threadIdx.x];
    float m = fmaxf(fmaxf(v.x, v.y), fmaxf(v.z, v.w));
    #pragma unroll
    for (int o = 16; o; o >>= 1) m = fmaxf(m, __shfl_xor_sync(0xffffffffu, m, o));
    __shared__ float sm[8];
    if ((threadIdx.x & 31) == 0) sm[threadIdx.x >> 5] = m;
    __syncthreads();
    float mm = sm[0];
    #pragma unroll
    for (int i = 1; i < 8; i++) mm = fmaxf(mm, sm[i]);
    v.x -= mm; v.y -= mm; v.z -= mm; v.w -= mm;
    rp[threadIdx.x] = v;
}

extern "C" void kernel_launch(void* const* d_in, const int* in_sizes, int n_in,
                              void* d_out, int out_size) {
    const float* anchor   = (const float*)d_in[0];
    const float* positive = (const float*)d_in[1];
    const float* W1 = (const float*)d_in[2];
    const float* b1 = (const float*)d_in[3];
    const float* W2 = (const float*)d_in[4];
    const float* b2 = (const float*)d_in[5];
    const float* Ww = (const float*)d_in[6];
    float* out = (float*)d_out;

    bf16 *ah, *al, *ph, *pl, *hh, *hl, *aph, *apl;
    bf16 *w1h, *w1l, *w2h, *w2l, *wwh, *wwl;
    cudaGetSymbolAddress((void**)&ah,  g_a_hi);
    cudaGetSymbolAddress((void**)&al,  g_a_lo);
    cudaGetSymbolAddress((void**)&ph,  g_pos_hi);
    cudaGetSymbolAddress((void**)&pl,  g_pos_lo);
    cudaGetSymbolAddress((void**)&hh,  g_hid_hi);
    cudaGetSymbolAddress((void**)&hl,  g_hid_lo);
    cudaGetSymbolAddress((void**)&aph, g_ap_hi);
    cudaGetSymbolAddress((void**)&apl, g_ap_lo);
    cudaGetSymbolAddress((void**)&w1h, g_w1_hi);
    cudaGetSymbolAddress((void**)&w1l, g_w1_lo);
    cudaGetSymbolAddress((void**)&w2h, g_w2_hi);
    cudaGetSymbolAddress((void**)&w2l, g_w2_lo);
    cudaGetSymbolAddress((void**)&wwh, g_ww_hi);
    cudaGetSymbolAddress((void**)&wwl, g_ww_lo);

    cudaFuncSetAttribute(mma_gemm<0>, cudaFuncAttributeMaxDynamicSharedMemorySize, SMEM_BYTES);
    cudaFuncSetAttribute(mma_gemm<1>, cudaFuncAttributeMaxDynamicSharedMemorySize, SMEM_BYTES);
    cudaFuncSetAttribute(mma_gemm<2>, cudaFuncAttributeMaxDynamicSharedMemorySize, SMEM_BYTES);
    cudaFuncSetAttribute(mma_gemm<3>, cudaFuncAttributeMaxDynamicSharedMemorySize, SMEM_BYTES);

    // prep
    transpose_split<<<dim3(16, 1024, 2), dim3(32, 8)>>>(anchor, ah, al, positive, ph, pl);
    split_w<<<512, 256>>>(W1, w1h, w1l, 131072);
    split_w<<<512, 256>>>(W2, w2h, w2l, 131072);
    split_w<<<256, 256>>>(Ww, wwh, wwl, 65536);

    // GEMM1: hidden = relu(a @ W1^T + b1)  [65536,512]
    mma_gemm<1><<<dim3(4, 512, 1), 256, SMEM_BYTES>>>(
        ah, al, 256, 0, w1h, w1l, 256, 0, 256,
        nullptr, 0, 0, hh, hl, 512, b1, nullptr, nullptr, 0);
    // GEMM2: aprime = a + hidden @ W2^T + b2  [65536,256]
    mma_gemm<2><<<dim3(2, 512, 1), 256, SMEM_BYTES>>>(
        hh, hl, 512, 0, w2h, w2l, 512, 0, 512,
        nullptr, 0, 0, aph, apl, 256, b2, ah, al, 256);
    // GEMM3: pred = aprime @ Ww^T  [65536,256]  (writes over a: anchor dead)
    mma_gemm<3><<<dim3(2, 512, 1), 256, SMEM_BYTES>>>(
        aph, apl, 256, 0, wwh, wwl, 256, 0, 256,
        nullptr, 0, 0, ah, al, 256, nullptr, nullptr, nullptr, 0);
    // GEMM4 (batched over p=64): logits[p] = pred_p @ pos_p^T  [1024,1024]
    mma_gemm<0><<<dim3(8, 8, 64), 256, SMEM_BYTES>>>(
        ah, al, 16384, 256, ph, pl, 16384, 256, 256,
        out, 1024, 1048576, nullptr, nullptr, 0, nullptr, nullptr, nullptr, 0);
    // subtract row max in-place
    rowmax_kernel<<<65536, 256>>>(out);
}

// round 8
// speedup vs baseline: 2.3143x; 1.1908x over previous
#include <cuda_runtime.h>
#include <cuda_bf16.h>

typedef __nv_bfloat16 bf16;

// ---------------------------------------------------------------------------
// StDimLocalLocalContrastModel via mma.sync bf16 (split-2 emulated fp32).
// ptxas target is sm_103 (no 'a' features): tcgen05 unavailable, HMMA path used.
//   P=64, B=1024, C=256, HID=512, M = B*P = 65536
// ---------------------------------------------------------------------------

#define BM 128
#define BN 128
#define BKK 32
#define PAD_ROW 40                    // bf16 elems per smem row (32 data + 8 pad)
#define TILE_BF (128 * PAD_ROW)       // elems per tile per stage
#define SMEM_BYTES (8 * TILE_BF * 2)  // 4 tensors x 2 stages x 10240 B = 81920

// ---- scratch (device globals; allocation-free) ----
__device__ bf16 g_a_hi  [16777216];   // [65536,256] anchor -> later pred (alias)
__device__ bf16 g_a_lo  [16777216];
__device__ bf16 g_pos_hi[16777216];   // [65536,256]
__device__ bf16 g_pos_lo[16777216];
__device__ bf16 g_hid_hi[33554432];   // [65536,512]
__device__ bf16 g_hid_lo[33554432];
__device__ bf16 g_ap_hi [16777216];   // [65536,256]
__device__ bf16 g_ap_lo [16777216];
__device__ bf16 g_w1_hi [131072], g_w1_lo[131072];   // [512,256]
__device__ bf16 g_w2_hi [131072], g_w2_lo[131072];   // [256,512]
__device__ bf16 g_ww_hi [65536],  g_ww_lo[65536];    // [256,256]

// ---- PTX helpers (all non-'a' ISA: cp.async sm_80, ldmatrix sm_75, mma sm_80) --
__device__ __forceinline__ void cp16(const bf16* src, bf16* dst) {
    unsigned d = (unsigned)__cvta_generic_to_shared(dst);
    asm volatile("cp.async.cg.shared.global [%0], [%1], 16;" :: "r"(d), "l"(src));
}
__device__ __forceinline__ void cp_commit() { asm volatile("cp.async.commit_group;"); }
template<int N> __device__ __forceinline__ void cp_wait() {
    asm volatile("cp.async.wait_group %0;" :: "n"(N));
}
__device__ __forceinline__ void ldsm4(unsigned* r, const bf16* p) {
    unsigned a = (unsigned)__cvta_generic_to_shared(p);
    asm volatile("ldmatrix.sync.aligned.m8n8.x4.shared.b16 {%0,%1,%2,%3}, [%4];"
        : "=r"(r[0]), "=r"(r[1]), "=r"(r[2]), "=r"(r[3]) : "r"(a));
}
__device__ __forceinline__ void mma_bf16(float* d, const unsigned* a, const unsigned* b) {
    asm volatile(
        "mma.sync.aligned.m16n8k16.row.col.f32.bf16.bf16.f32 "
        "{%0,%1,%2,%3}, {%4,%5,%6,%7}, {%8,%9}, {%0,%1,%2,%3};"
        : "+f"(d[0]), "+f"(d[1]), "+f"(d[2]), "+f"(d[3])
        : "r"(a[0]), "r"(a[1]), "r"(a[2]), "r"(a[3]), "r"(b[0]), "r"(b[1]));
}

// ---------------------------------------------------------------------------
// mma_gemm: C[m,n] = sum_k A[m,k]*B[n,k], split-bf16 emulated fp32.
// MODE 0: fp32 out   MODE 1: relu(acc+bias)->hi/lo
// MODE 2: acc+bias+resid->hi/lo   MODE 3: plain->hi/lo
// CTA 128x128, BK=32, 8 warps (2x4), warp tile 64x32.  2 CTAs/SM target.
// ---------------------------------------------------------------------------
template<int MODE>
__global__ __launch_bounds__(256, 2)
void mma_gemm(const bf16* __restrict__ Ahi, const bf16* __restrict__ Alo, long As, long Ab,
              const bf16* __restrict__ Bhi, const bf16* __restrict__ Blo, long Bs, long Bb,
              int K,
              float* __restrict__ Cf, long Cs, long Cb,
              bf16* __restrict__ Ohi, bf16* __restrict__ Olo, long Os,
              const float* __restrict__ bias,
              const bf16* __restrict__ Rhi, const bf16* __restrict__ Rlo, long Rs)
{
    extern __shared__ bf16 smem[];
    bf16* sAh = smem;
    bf16* sAl = smem + 2 * TILE_BF;
    bf16* sBh = smem + 4 * TILE_BF;
    bf16* sBl = smem + 6 * TILE_BF;

    const int tid = threadIdx.x;
    const int wid = tid >> 5;
    const int lane = tid & 31;
    const long z = blockIdx.z;

    const bf16* gAh = Ahi + z * Ab + (long)blockIdx.y * BM * As;
    const bf16* gAl = Alo + z * Ab + (long)blockIdx.y * BM * As;
    const bf16* gBh = Bhi + z * Bb + (long)blockIdx.x * BN * Bs;
    const bf16* gBl = Blo + z * Bb + (long)blockIdx.x * BN * Bs;

    // loader: 128 rows x 32 k = 512 16B chunks per tile, 2 per thread
    auto loadTile = [&](const bf16* g, long stride, int k0, bf16* dst) {
        #pragma unroll
        for (int it = 0; it < 2; it++) {
            int c = tid + it * 256;
            int r = c >> 2, kc = c & 3;
            cp16(g + (long)r * stride + k0 + kc * 8, dst + r * PAD_ROW + kc * 8);
        }
    };
    auto loadAll = [&](int kt, int s) {
        int k0 = kt * BKK;
        loadTile(gAh, As, k0, sAh + s * TILE_BF);
        loadTile(gAl, As, k0, sAl + s * TILE_BF);
        loadTile(gBh, Bs, k0, sBh + s * TILE_BF);
        loadTile(gBl, Bs, k0, sBl + s * TILE_BF);
        cp_commit();
    };

    float acc[4][4][4];
    #pragma unroll
    for (int i = 0; i < 4; i++)
        #pragma unroll
        for (int j = 0; j < 4; j++)
            #pragma unroll
            for (int q = 0; q < 4; q++) acc[i][j][q] = 0.0f;

    const int wm = (wid >> 2) * 64;            // warp m offset
    const int wn = (wid & 3) * 32;             // warp n offset
    // ldmatrix lane->address mapping (see PTX spec m16n8k16 row.col frags)
    const int aRow = (lane & 7) + ((lane >> 3) & 1) * 8;
    const int aColH = ((lane >> 4) & 1) * 8;
    const int bRow = (lane & 7) + ((lane >> 4) & 1) * 8;
    const int bColH = ((lane >> 3) & 1) * 8;

    loadAll(0, 0);

    const int nk = K / BKK;
    for (int kt = 0; kt < nk; kt++) {
        if (kt + 1 < nk) { loadAll(kt + 1, (kt + 1) & 1); cp_wait<1>(); }
        else             { cp_wait<0>(); }
        __syncthreads();

        const int s = kt & 1;
        const bf16* Ah = sAh + s * TILE_BF;
        const bf16* Al = sAl + s * TILE_BF;
        const bf16* Bh = sBh + s * TILE_BF;
        const bf16* Bl = sBl + s * TILE_BF;

        #pragma unroll
        for (int kh = 0; kh < BKK; kh += 16) {
            unsigned Bh4[2][4], Bl4[2][4];
            #pragma unroll
            for (int nj = 0; nj < 2; nj++) {
                const bf16* bp = Bh + (wn + nj * 16 + bRow) * PAD_ROW + kh + bColH;
                ldsm4(Bh4[nj], bp);
                const bf16* bq = Bl + (wn + nj * 16 + bRow) * PAD_ROW + kh + bColH;
                ldsm4(Bl4[nj], bq);
            }
            #pragma unroll
            for (int mi = 0; mi < 4; mi++) {
                unsigned Ah4[4], Al4[4];
                const bf16* ap = Ah + (wm + mi * 16 + aRow) * PAD_ROW + kh + aColH;
                ldsm4(Ah4, ap);
                const bf16* aq = Al + (wm + mi * 16 + aRow) * PAD_ROW + kh + aColH;
                ldsm4(Al4, aq);
                #pragma unroll
                for (int ni = 0; ni < 4; ni++) {
                    const unsigned* bh = &Bh4[ni >> 1][(ni & 1) * 2];
                    const unsigned* bl = &Bl4[ni >> 1][(ni & 1) * 2];
                    mma_bf16(acc[mi][ni], Ah4, bh);   // hi*hi
                    mma_bf16(acc[mi][ni], Ah4, bl);   // hi*lo
                    mma_bf16(acc[mi][ni], Al4, bh);   // lo*hi
                }
            }
        }
        __syncthreads();
    }

    // ---- epilogue ----
    const int quad = lane >> 2, qt = lane & 3;
    const long rowBase = (long)blockIdx.y * BM + wm;
    const int colBase = blockIdx.x * BN + wn;

    #pragma unroll
    for (int mi = 0; mi < 4; mi++) {
        #pragma unroll
        for (int ni = 0; ni < 4; ni++) {
            #pragma unroll
            for (int half = 0; half < 2; half++) {
                long m = rowBase + mi * 16 + quad + half * 8;
                int n = colBase + ni * 8 + qt * 2;
                float v0 = acc[mi][ni][half * 2 + 0];
                float v1 = acc[mi][ni][half * 2 + 1];
                if (MODE == 0) {
                    *(float2*)(Cf + z * Cb + m * Cs + n) = make_float2(v0, v1);
                } else {
                    if (MODE == 1) {
                        v0 = fmaxf(v0 + bias[n], 0.0f);
                        v1 = fmaxf(v1 + bias[n + 1], 0.0f);
                    } else if (MODE == 2) {
                        __nv_bfloat162 rh = *(const __nv_bfloat162*)(Rhi + m * Rs + n);
                        __nv_bfloat162 rl = *(const __nv_bfloat162*)(Rlo + m * Rs + n);
                        v0 += bias[n]     + __bfloat162float(rh.x) + __bfloat162float(rl.x);
                        v1 += bias[n + 1] + __bfloat162float(rh.y) + __bfloat162float(rl.y);
                    }
                    bf16 h0 = __float2bfloat16(v0);
                    bf16 h1 = __float2bfloat16(v1);
                    bf16 l0 = __float2bfloat16(v0 - __bfloat162float(h0));
                    bf16 l1 = __float2bfloat16(v1 - __bfloat162float(h1));
                    __nv_bfloat162 hp; hp.x = h0; hp.y = h1;
                    __nv_bfloat162 lp; lp.x = l0; lp.y = l1;
                    *(__nv_bfloat162*)(Ohi + m * Os + n) = hp;
                    *(__nv_bfloat162*)(Olo + m * Os + n) = lp;
                }
            }
        }
    }
}

// ---------------------------------------------------------------------------
// prep: [1024][256][64] fp32 -> hi/lo bf16 [(b*64+p)][c]
// ---------------------------------------------------------------------------
__global__ void transpose_split(const float* __restrict__ in0, bf16* __restrict__ h0, bf16* __restrict__ l0,
                                const float* __restrict__ in1, bf16* __restrict__ h1, bf16* __restrict__ l1) {
    __shared__ float t[32][33];
    const float* in = blockIdx.z ? in1 : in0;
    bf16* oh = blockIdx.z ? h1 : h0;
    bf16* ol = blockIdx.z ? l1 : l0;
    int b  = blockIdx.y;
    int c0 = (blockIdx.x & 7) * 32;
    int p0 = (blockIdx.x >> 3) * 32;
    const float* src = in + (long)b * 16384;
    #pragma unroll
    for (int j = 0; j < 32; j += 8)
        t[threadIdx.y + j][threadIdx.x] = src[(c0 + threadIdx.y + j) * 64 + p0 + threadIdx.x];
    __syncthreads();
    #pragma unroll
    for (int j = 0; j < 32; j += 8) {
        float v = t[threadIdx.x][threadIdx.y + j];
        long rowoff = ((long)b * 64 + p0 + threadIdx.y + j) * 256 + c0 + threadIdx.x;
        bf16 h = __float2bfloat16(v);
        oh[rowoff] = h;
        ol[rowoff] = __float2bfloat16(v - __bfloat162float(h));
    }
}

// all three weight splits in one launch: W1 (131072) | W2 (131072) | Ww (65536)
__global__ void split_w3(const float* __restrict__ W1, bf16* __restrict__ w1h, bf16* __restrict__ w1l,
                         const float* __restrict__ W2, bf16* __restrict__ w2h, bf16* __restrict__ w2l,
                         const float* __restrict__ Ww, bf16* __restrict__ wwh, bf16* __restrict__ wwl) {
    int i = blockIdx.x * 256 + threadIdx.x;
    const float* w; bf16 *hi, *lo; int off;
    if (i < 131072)      { w = W1; hi = w1h; lo = w1l; off = i; }
    else if (i < 262144) { w = W2; hi = w2h; lo = w2l; off = i - 131072; }
    else                 { w = Ww; hi = wwh; lo = wwl; off = i - 262144; }
    float v = w[off];
    bf16 h = __float2bfloat16(v);
    hi[off] = h;
    lo[off] = __float2bfloat16(v - __bfloat162float(h));
}

// subtract row max in-place, row = 1024 floats
__global__ void rowmax_kernel(float* __restrict__ out) {
    long row = blockIdx.x;
    float4* rp = (float4*)(out + row * 1024);
    float4 v = rp[threadIdx.x];
    float m = fmaxf(fmaxf(v.x, v.y), fmaxf(v.z, v.w));
    #pragma unroll
    for (int o = 16; o; o >>= 1) m = fmaxf(m, __shfl_xor_sync(0xffffffffu, m, o));
    __shared__ float sm[8];
    if ((threadIdx.x & 31) == 0) sm[threadIdx.x >> 5] = m;
    __syncthreads();
    float mm = sm[0];
    #pragma unroll
    for (int i = 1; i < 8; i++) mm = fmaxf(mm, sm[i]);
    v.x -= mm; v.y -= mm; v.z -= mm; v.w -= mm;
    rp[threadIdx.x] = v;
}

extern "C" void kernel_launch(void* const* d_in, const int* in_sizes, int n_in,
                              void* d_out, int out_size) {
    const float* anchor   = (const float*)d_in[0];
    const float* positive = (const float*)d_in[1];
    const float* W1 = (const float*)d_in[2];
    const float* b1 = (const float*)d_in[3];
    const float* W2 = (const float*)d_in[4];
    const float* b2 = (const float*)d_in[5];
    const float* Ww = (const float*)d_in[6];
    float* out = (float*)d_out;

    bf16 *ah, *al, *ph, *pl, *hh, *hl, *aph, *apl;
    bf16 *w1h, *w1l, *w2h, *w2l, *wwh, *wwl;
    cudaGetSymbolAddress((void**)&ah,  g_a_hi);
    cudaGetSymbolAddress((void**)&al,  g_a_lo);
    cudaGetSymbolAddress((void**)&ph,  g_pos_hi);
    cudaGetSymbolAddress((void**)&pl,  g_pos_lo);
    cudaGetSymbolAddress((void**)&hh,  g_hid_hi);
    cudaGetSymbolAddress((void**)&hl,  g_hid_lo);
    cudaGetSymbolAddress((void**)&aph, g_ap_hi);
    cudaGetSymbolAddress((void**)&apl, g_ap_lo);
    cudaGetSymbolAddress((void**)&w1h, g_w1_hi);
    cudaGetSymbolAddress((void**)&w1l, g_w1_lo);
    cudaGetSymbolAddress((void**)&w2h, g_w2_hi);
    cudaGetSymbolAddress((void**)&w2l, g_w2_lo);
    cudaGetSymbolAddress((void**)&wwh, g_ww_hi);
    cudaGetSymbolAddress((void**)&wwl, g_ww_lo);

    cudaFuncSetAttribute(mma_gemm<0>, cudaFuncAttributeMaxDynamicSharedMemorySize, SMEM_BYTES);
    cudaFuncSetAttribute(mma_gemm<1>, cudaFuncAttributeMaxDynamicSharedMemorySize, SMEM_BYTES);
    cudaFuncSetAttribute(mma_gemm<2>, cudaFuncAttributeMaxDynamicSharedMemorySize, SMEM_BYTES);
    cudaFuncSetAttribute(mma_gemm<3>, cudaFuncAttributeMaxDynamicSharedMemorySize, SMEM_BYTES);

    // prep
    transpose_split<<<dim3(16, 1024, 2), dim3(32, 8)>>>(anchor, ah, al, positive, ph, pl);
    split_w3<<<1280, 256>>>(W1, w1h, w1l, W2, w2h, w2l, Ww, wwh, wwl);

    // GEMM1: hidden = relu(a @ W1^T + b1)  [65536,512]
    mma_gemm<1><<<dim3(4, 512, 1), 256, SMEM_BYTES>>>(
        ah, al, 256, 0, w1h, w1l, 256, 0, 256,
        nullptr, 0, 0, hh, hl, 512, b1, nullptr, nullptr, 0);
    // GEMM2: aprime = a + hidden @ W2^T + b2  [65536,256]
    mma_gemm<2><<<dim3(2, 512, 1), 256, SMEM_BYTES>>>(
        hh, hl, 512, 0, w2h, w2l, 512, 0, 512,
        nullptr, 0, 0, aph, apl, 256, b2, ah, al, 256);
    // GEMM3: pred = aprime @ Ww^T  [65536,256]  (writes over a: anchor dead)
    mma_gemm<3><<<dim3(2, 512, 1), 256, SMEM_BYTES>>>(
        aph, apl, 256, 0, wwh, wwl, 256, 0, 256,
        nullptr, 0, 0, ah, al, 256, nullptr, nullptr, nullptr, 0);
    // GEMM4 (batched over p=64): logits[p] = pred_p @ pos_p^T  [1024,1024]
    mma_gemm<0><<<dim3(8, 8, 64), 256, SMEM_BYTES>>>(
        ah, al, 16384, 256, ph, pl, 16384, 256, 256,
        out, 1024, 1048576, nullptr, nullptr, 0, nullptr, nullptr, nullptr, 0);
    // subtract row max in-place
    rowmax_kernel<<<65536, 256>>>(out);
}

// round 9
// speedup vs baseline: 2.5388x; 1.0970x over previous
#include <cuda_runtime.h>
#include <cuda_bf16.h>

typedef __nv_bfloat16 bf16;

// ---------------------------------------------------------------------------
// StDimLocalLocalContrastModel via mma.sync bf16 (split-2 emulated fp32).
// ptxas target is sm_103 (no 'a' features): tcgen05 unavailable, HMMA path used.
//   P=64, B=1024, C=256, HID=512, M = B*P = 65536
// 3-stage cp.async pipeline, XOR-swizzled smem (no padding), 2 CTAs/SM.
// ---------------------------------------------------------------------------

#define BM 128
#define BN 128
#define BKK 32
#define TILE_ELEMS 4096               // 128 rows x 32 bf16 = 8 KB
#define NSTAGE 3
#define SMEM_BYTES (4 * NSTAGE * TILE_ELEMS * 2)   // 98304 B = 96 KB

// ---- scratch (device globals; allocation-free) ----
__device__ bf16 g_a_hi  [16777216];   // [65536,256] anchor -> later pred (alias)
__device__ bf16 g_a_lo  [16777216];
__device__ bf16 g_pos_hi[16777216];   // [65536,256]
__device__ bf16 g_pos_lo[16777216];
__device__ bf16 g_hid_hi[33554432];   // [65536,512]
__device__ bf16 g_hid_lo[33554432];
__device__ bf16 g_ap_hi [16777216];   // [65536,256]
__device__ bf16 g_ap_lo [16777216];
__device__ bf16 g_w1_hi [131072], g_w1_lo[131072];   // [512,256]
__device__ bf16 g_w2_hi [131072], g_w2_lo[131072];   // [256,512]
__device__ bf16 g_ww_hi [65536],  g_ww_lo[65536];    // [256,256]

// ---- PTX helpers (all non-'a' ISA: cp.async sm_80, ldmatrix sm_75, mma sm_80) --
__device__ __forceinline__ void cp16(const bf16* src, bf16* dst) {
    unsigned d = (unsigned)__cvta_generic_to_shared(dst);
    asm volatile("cp.async.cg.shared.global [%0], [%1], 16;" :: "r"(d), "l"(src));
}
__device__ __forceinline__ void cp_commit() { asm volatile("cp.async.commit_group;"); }
template<int N> __device__ __forceinline__ void cp_wait() {
    asm volatile("cp.async.wait_group %0;" :: "n"(N));
}
__device__ __forceinline__ void ldsm4(unsigned* r, const bf16* p) {
    unsigned a = (unsigned)__cvta_generic_to_shared(p);
    asm volatile("ldmatrix.sync.aligned.m8n8.x4.shared.b16 {%0,%1,%2,%3}, [%4];"
        : "=r"(r[0]), "=r"(r[1]), "=r"(r[2]), "=r"(r[3]) : "r"(a));
}
__device__ __forceinline__ void mma_bf16(float* d, const unsigned* a, const unsigned* b) {
    asm volatile(
        "mma.sync.aligned.m16n8k16.row.col.f32.bf16.bf16.f32 "
        "{%0,%1,%2,%3}, {%4,%5,%6,%7}, {%8,%9}, {%0,%1,%2,%3};"
        : "+f"(d[0]), "+f"(d[1]), "+f"(d[2]), "+f"(d[3])
        : "r"(a[0]), "r"(a[1]), "r"(a[2]), "r"(a[3]), "r"(b[0]), "r"(b[1]));
}

// swizzled address within a 128x32 tile: row stride 32 elems, 4x16B chunks/row,
// chunk' = chunk ^ ((row>>1)&3)  -> conflict-free for cp.async STS and ldmatrix.
__device__ __forceinline__ const bf16* swz(const bf16* tile, int row, int kcol) {
    int chunk = kcol >> 3;
    return tile + row * 32 + ((chunk ^ ((row >> 1) & 3)) << 3);
}

// ---------------------------------------------------------------------------
// mma_gemm: C[m,n] = sum_k A[m,k]*B[n,k], split-bf16 emulated fp32.
// MODE 0: fp32 out   MODE 1: relu(acc+bias)->hi/lo
// MODE 2: acc+bias+resid->hi/lo   MODE 3: plain->hi/lo
// CTA 128x128, BK=32, 8 warps (2x4), warp tile 64x32, 3-stage pipeline.
// ---------------------------------------------------------------------------
template<int MODE>
__global__ __launch_bounds__(256, 2)
void mma_gemm(const bf16* __restrict__ Ahi, const bf16* __restrict__ Alo, long As, long Ab,
              const bf16* __restrict__ Bhi, const bf16* __restrict__ Blo, long Bs, long Bb,
              int K,
              float* __restrict__ Cf, long Cs, long Cb,
              bf16* __restrict__ Ohi, bf16* __restrict__ Olo, long Os,
              const float* __restrict__ bias,
              const bf16* __restrict__ Rhi, const bf16* __restrict__ Rlo, long Rs)
{
    extern __shared__ bf16 smem[];
    bf16* sAh = smem;                           // [NSTAGE][4096]
    bf16* sAl = smem + NSTAGE * TILE_ELEMS;
    bf16* sBh = smem + 2 * NSTAGE * TILE_ELEMS;
    bf16* sBl = smem + 3 * NSTAGE * TILE_ELEMS;

    const int tid = threadIdx.x;
    const int wid = tid >> 5;
    const int lane = tid & 31;
    const long z = blockIdx.z;

    const bf16* gAh = Ahi + z * Ab + (long)blockIdx.y * BM * As;
    const bf16* gAl = Alo + z * Ab + (long)blockIdx.y * BM * As;
    const bf16* gBh = Bhi + z * Bb + (long)blockIdx.x * BN * Bs;
    const bf16* gBl = Blo + z * Bb + (long)blockIdx.x * BN * Bs;

    // loader: 128 rows x 32 k = 512 16B chunks per tile, 2 per thread
    auto loadTile = [&](const bf16* g, long stride, int k0, bf16* dst) {
        #pragma unroll
        for (int it = 0; it < 2; it++) {
            int c = tid + it * 256;
            int r = c >> 2, kc = c & 3;
            cp16(g + (long)r * stride + k0 + kc * 8,
                 dst + r * 32 + ((kc ^ ((r >> 1) & 3)) << 3));
        }
    };
    auto loadAll = [&](int kt, int s) {
        int k0 = kt * BKK;
        loadTile(gAh, As, k0, sAh + s * TILE_ELEMS);
        loadTile(gAl, As, k0, sAl + s * TILE_ELEMS);
        loadTile(gBh, Bs, k0, sBh + s * TILE_ELEMS);
        loadTile(gBl, Bs, k0, sBl + s * TILE_ELEMS);
        cp_commit();
    };

    float acc[4][4][4];
    #pragma unroll
    for (int i = 0; i < 4; i++)
        #pragma unroll
        for (int j = 0; j < 4; j++)
            #pragma unroll
            for (int q = 0; q < 4; q++) acc[i][j][q] = 0.0f;

    const int wm = (wid >> 2) * 64;            // warp m offset
    const int wn = (wid & 3) * 32;             // warp n offset
    // ldmatrix lane->address mapping (PTX spec m16n8k16 row.col frags)
    const int aRow = (lane & 7) + ((lane >> 3) & 1) * 8;
    const int aColH = ((lane >> 4) & 1) * 8;
    const int bRow = (lane & 7) + ((lane >> 4) & 1) * 8;
    const int bColH = ((lane >> 3) & 1) * 8;

    const int nk = K / BKK;
    loadAll(0, 0);
    loadAll(1, 1);

    for (int kt = 0; kt < nk; kt++) {
        // stage kt's group must be complete: exactly one younger group may pend.
        if (kt + 1 < nk) cp_wait<1>(); else cp_wait<0>();
        __syncthreads();   // make cp.async data visible to all warps; also
                           // guarantees stage (kt+2)%3 (= (kt-1)%3) is done being read.
        if (kt + 2 < nk) loadAll(kt + 2, (kt + 2) % NSTAGE);

        const int s = kt % NSTAGE;
        const bf16* Ah = sAh + s * TILE_ELEMS;
        const bf16* Al = sAl + s * TILE_ELEMS;
        const bf16* Bh = sBh + s * TILE_ELEMS;
        const bf16* Bl = sBl + s * TILE_ELEMS;

        #pragma unroll
        for (int kh = 0; kh < BKK; kh += 16) {
            unsigned Bh4[2][4], Bl4[2][4];
            #pragma unroll
            for (int nj = 0; nj < 2; nj++) {
                ldsm4(Bh4[nj], swz(Bh, wn + nj * 16 + bRow, kh + bColH));
                ldsm4(Bl4[nj], swz(Bl, wn + nj * 16 + bRow, kh + bColH));
            }
            #pragma unroll
            for (int mi = 0; mi < 4; mi++) {
                unsigned Ah4[4], Al4[4];
                ldsm4(Ah4, swz(Ah, wm + mi * 16 + aRow, kh + aColH));
                ldsm4(Al4, swz(Al, wm + mi * 16 + aRow, kh + aColH));
                #pragma unroll
                for (int ni = 0; ni < 4; ni++) {
                    const unsigned* bh = &Bh4[ni >> 1][(ni & 1) * 2];
                    const unsigned* bl = &Bl4[ni >> 1][(ni & 1) * 2];
                    mma_bf16(acc[mi][ni], Ah4, bh);   // hi*hi
                    mma_bf16(acc[mi][ni], Ah4, bl);   // hi*lo
                    mma_bf16(acc[mi][ni], Al4, bh);   // lo*hi
                }
            }
        }
    }

    // ---- epilogue ----
    const int quad = lane >> 2, qt = lane & 3;
    const long rowBase = (long)blockIdx.y * BM + wm;
    const int colBase = blockIdx.x * BN + wn;

    #pragma unroll
    for (int mi = 0; mi < 4; mi++) {
        #pragma unroll
        for (int ni = 0; ni < 4; ni++) {
            #pragma unroll
            for (int half = 0; half < 2; half++) {
                long m = rowBase + mi * 16 + quad + half * 8;
                int n = colBase + ni * 8 + qt * 2;
                float v0 = acc[mi][ni][half * 2 + 0];
                float v1 = acc[mi][ni][half * 2 + 1];
                if (MODE == 0) {
                    *(float2*)(Cf + z * Cb + m * Cs + n) = make_float2(v0, v1);
                } else {
                    if (MODE == 1) {
                        v0 = fmaxf(v0 + bias[n], 0.0f);
                        v1 = fmaxf(v1 + bias[n + 1], 0.0f);
                    } else if (MODE == 2) {
                        __nv_bfloat162 rh = *(const __nv_bfloat162*)(Rhi + m * Rs + n);
                        __nv_bfloat162 rl = *(const __nv_bfloat162*)(Rlo + m * Rs + n);
                        v0 += bias[n]     + __bfloat162float(rh.x) + __bfloat162float(rl.x);
                        v1 += bias[n + 1] + __bfloat162float(rh.y) + __bfloat162float(rl.y);
                    }
                    bf16 h0 = __float2bfloat16(v0);
                    bf16 h1 = __float2bfloat16(v1);
                    bf16 l0 = __float2bfloat16(v0 - __bfloat162float(h0));
                    bf16 l1 = __float2bfloat16(v1 - __bfloat162float(h1));
                    __nv_bfloat162 hp; hp.x = h0; hp.y = h1;
                    __nv_bfloat162 lp; lp.x = l0; lp.y = l1;
                    *(__nv_bfloat162*)(Ohi + m * Os + n) = hp;
                    *(__nv_bfloat162*)(Olo + m * Os + n) = lp;
                }
            }
        }
    }
}

// ---------------------------------------------------------------------------
// prep: [1024][256][64] fp32 -> hi/lo bf16 [(b*64+p)][c]
// ---------------------------------------------------------------------------
__global__ void transpose_split(const float* __restrict__ in0, bf16* __restrict__ h0, bf16* __restrict__ l0,
                                const float* __restrict__ in1, bf16* __restrict__ h1, bf16* __restrict__ l1) {
    __shared__ float t[32][33];
    const float* in = blockIdx.z ? in1 : in0;
    bf16* oh = blockIdx.z ? h1 : h0;
    bf16* ol = blockIdx.z ? l1 : l0;
    int b  = blockIdx.y;
    int c0 = (blockIdx.x & 7) * 32;
    int p0 = (blockIdx.x >> 3) * 32;
    const float* src = in + (long)b * 16384;
    #pragma unroll
    for (int j = 0; j < 32; j += 8)
        t[threadIdx.y + j][threadIdx.x] = src[(c0 + threadIdx.y + j) * 64 + p0 + threadIdx.x];
    __syncthreads();
    #pragma unroll
    for (int j = 0; j < 32; j += 8) {
        float v = t[threadIdx.x][threadIdx.y + j];
        long rowoff = ((long)b * 64 + p0 + threadIdx.y + j) * 256 + c0 + threadIdx.x;
        bf16 h = __float2bfloat16(v);
        oh[rowoff] = h;
        ol[rowoff] = __float2bfloat16(v - __bfloat162float(h));
    }
}

// all three weight splits in one launch: W1 (131072) | W2 (131072) | Ww (65536)
__global__ void split_w3(const float* __restrict__ W1, bf16* __restrict__ w1h, bf16* __restrict__ w1l,
                         const float* __restrict__ W2, bf16* __restrict__ w2h, bf16* __restrict__ w2l,
                         const float* __restrict__ Ww, bf16* __restrict__ wwh, bf16* __restrict__ wwl) {
    int i = blockIdx.x * 256 + threadIdx.x;
    const float* w; bf16 *hi, *lo; int off;
    if (i < 131072)      { w = W1; hi = w1h; lo = w1l; off = i; }
    else if (i < 262144) { w = W2; hi = w2h; lo = w2l; off = i - 131072; }
    else                 { w = Ww; hi = wwh; lo = wwl; off = i - 262144; }
    float v = w[off];
    bf16 h = __float2bfloat16(v);
    hi[off] = h;
    lo[off] = __float2bfloat16(v - __bfloat162float(h));
}

// subtract row max in-place, row = 1024 floats
__global__ void rowmax_kernel(float* __restrict__ out) {
    long row = blockIdx.x;
    float4* rp = (float4*)(out + row * 1024);
    float4 v = rp[threadIdx.x];
    float m = fmaxf(fmaxf(v.x, v.y), fmaxf(v.z, v.w));
    #pragma unroll
    for (int o = 16; o; o >>= 1) m = fmaxf(m, __shfl_xor_sync(0xffffffffu, m, o));
    __shared__ float sm[8];
    if ((threadIdx.x & 31) == 0) sm[threadIdx.x >> 5] = m;
    __syncthreads();
    float mm = sm[0];
    #pragma unroll
    for (int i = 1; i < 8; i++) mm = fmaxf(mm, sm[i]);
    v.x -= mm; v.y -= mm; v.z -= mm; v.w -= mm;
    rp[threadIdx.x] = v;
}

extern "C" void kernel_launch(void* const* d_in, const int* in_sizes, int n_in,
                              void* d_out, int out_size) {
    const float* anchor   = (const float*)d_in[0];
    const float* positive = (const float*)d_in[1];
    const float* W1 = (const float*)d_in[2];
    const float* b1 = (const float*)d_in[3];
    const float* W2 = (const float*)d_in[4];
    const float* b2 = (const float*)d_in[5];
    const float* Ww = (const float*)d_in[6];
    float* out = (float*)d_out;

    bf16 *ah, *al, *ph, *pl, *hh, *hl, *aph, *apl;
    bf16 *w1h, *w1l, *w2h, *w2l, *wwh, *wwl;
    cudaGetSymbolAddress((void**)&ah,  g_a_hi);
    cudaGetSymbolAddress((void**)&al,  g_a_lo);
    cudaGetSymbolAddress((void**)&ph,  g_pos_hi);
    cudaGetSymbolAddress((void**)&pl,  g_pos_lo);
    cudaGetSymbolAddress((void**)&hh,  g_hid_hi);
    cudaGetSymbolAddress((void**)&hl,  g_hid_lo);
    cudaGetSymbolAddress((void**)&aph, g_ap_hi);
    cudaGetSymbolAddress((void**)&apl, g_ap_lo);
    cudaGetSymbolAddress((void**)&w1h, g_w1_hi);
    cudaGetSymbolAddress((void**)&w1l, g_w1_lo);
    cudaGetSymbolAddress((void**)&w2h, g_w2_hi);
    cudaGetSymbolAddress((void**)&w2l, g_w2_lo);
    cudaGetSymbolAddress((void**)&wwh, g_ww_hi);
    cudaGetSymbolAddress((void**)&wwl, g_ww_lo);

    cudaFuncSetAttribute(mma_gemm<0>, cudaFuncAttributeMaxDynamicSharedMemorySize, SMEM_BYTES);
    cudaFuncSetAttribute(mma_gemm<1>, cudaFuncAttributeMaxDynamicSharedMemorySize, SMEM_BYTES);
    cudaFuncSetAttribute(mma_gemm<2>, cudaFuncAttributeMaxDynamicSharedMemorySize, SMEM_BYTES);
    cudaFuncSetAttribute(mma_gemm<3>, cudaFuncAttributeMaxDynamicSharedMemorySize, SMEM_BYTES);

    // prep
    transpose_split<<<dim3(16, 1024, 2), dim3(32, 8)>>>(anchor, ah, al, positive, ph, pl);
    split_w3<<<1280, 256>>>(W1, w1h, w1l, W2, w2h, w2l, Ww, wwh, wwl);

    // GEMM1: hidden = relu(a @ W1^T + b1)  [65536,512]
    mma_gemm<1><<<dim3(4, 512, 1), 256, SMEM_BYTES>>>(
        ah, al, 256, 0, w1h, w1l, 256, 0, 256,
        nullptr, 0, 0, hh, hl, 512, b1, nullptr, nullptr, 0);
    // GEMM2: aprime = a + hidden @ W2^T + b2  [65536,256]
    mma_gemm<2><<<dim3(2, 512, 1), 256, SMEM_BYTES>>>(
        hh, hl, 512, 0, w2h, w2l, 512, 0, 512,
        nullptr, 0, 0, aph, apl, 256, b2, ah, al, 256);
    // GEMM3: pred = aprime @ Ww^T  [65536,256]  (writes over a: anchor dead)
    mma_gemm<3><<<dim3(2, 512, 1), 256, SMEM_BYTES>>>(
        aph, apl, 256, 0, wwh, wwl, 256, 0, 256,
        nullptr, 0, 0, ah, al, 256, nullptr, nullptr, nullptr, 0);
    // GEMM4 (batched over p=64): logits[p] = pred_p @ pos_p^T  [1024,1024]
    mma_gemm<0><<<dim3(8, 8, 64), 256, SMEM_BYTES>>>(
        ah, al, 16384, 256, ph, pl, 16384, 256, 256,
        out, 1024, 1048576, nullptr, nullptr, 0, nullptr, nullptr, nullptr, 0);
    // subtract row max in-place
    rowmax_kernel<<<65536, 256>>>(out);
}